// round 1
// baseline (speedup 1.0000x reference)
#include <cuda_runtime.h>

#define N_B 8
#define A_N 131072
#define T_N 64
typedef unsigned long long ull;

// Scratch (static __device__ — no allocations allowed)
__device__ ull           g_gt_best[N_B * T_N];     // packed (iou_bits<<32 | ~anchor)
__device__ float         g_iou_max[N_B * A_N];
__device__ unsigned char g_best_g [N_B * A_N];
__device__ signed char   g_cls0  [N_B * A_N];
__device__ ull           g_thresh[N_B * 2];        // [pos_th, neg_th] per batch

__global__ void k_init() {
    int i = blockIdx.x * blockDim.x + threadIdx.x;
    if (i < N_B * T_N) g_gt_best[i] = 0ull;
}

__global__ void k_iou(const float4* __restrict__ anchors, const float4* __restrict__ gts) {
    const int b   = blockIdx.y;
    const int a   = blockIdx.x * blockDim.x + threadIdx.x;
    const int tid = threadIdx.x;

    __shared__ float sy1[T_N], sx1[T_N], sy2[T_N], sx2[T_N], sga[T_N];
    __shared__ ull   sbest[T_N];

    if (tid < T_N) {
        float4 g = gts[b * T_N + tid];
        sy1[tid] = g.x; sx1[tid] = g.y; sy2[tid] = g.z; sx2[tid] = g.w;
        sga[tid] = (g.z - g.x) * (g.w - g.y);
        sbest[tid] = 0ull;
    }
    __syncthreads();

    float4 box = anchors[b * A_N + a];
    bool inb = (box.x >= 0.f) && (box.y >= 0.f) && (box.z <= 1.f) && (box.w <= 1.f);
    if (!inb) { box.x = box.y = box.z = box.w = 0.f; }
    const float aarea = (box.z - box.x) * (box.w - box.y);

    float mymax = -1.f;
    int   myg   = 0;
    const unsigned ainv = 0xFFFFFFFFu - (unsigned)a;  // max-key => min anchor idx (first-max tie-break)

    #pragma unroll
    for (int g = 0; g < T_N; ++g) {
        float ih = fminf(box.z, sy2[g]) - fmaxf(box.x, sy1[g]);
        float iw = fminf(box.w, sx2[g]) - fmaxf(box.y, sx1[g]);
        ih = fmaxf(ih, 0.f);
        iw = fmaxf(iw, 0.f);
        float inter = ih * iw;
        float iou = 0.f;
        if (inter > 0.f) {
            float un = aarea + sga[g] - inter;     // un >= garea > 0 whenever inter > 0
            iou = __fdiv_rn(inter, un);            // IEEE: match XLA's div exactly
        }
        if (iou > mymax) { mymax = iou; myg = g; } // strict > => first-max argmax over g
        ull key = ((ull)__float_as_uint(iou) << 32) | ainv;
        if (key > sbest[g]) atomicMax(&sbest[g], key);  // read-filter then shared atomic
    }

    g_iou_max[b * A_N + a] = mymax;   // mymax >= 0 always (iou>=0 beats -1 at g=0)
    g_best_g [b * A_N + a] = (unsigned char)myg;

    __syncthreads();
    if (tid < T_N && sbest[tid]) atomicMax(&g_gt_best[b * T_N + tid], sbest[tid]);
}

__global__ void k_cls() {
    const int b = blockIdx.y;
    const int a = blockIdx.x * blockDim.x + threadIdx.x;
    __shared__ int sba[T_N];
    if (threadIdx.x < T_N)
        sba[threadIdx.x] =
            (int)(0xFFFFFFFFu - (unsigned)(g_gt_best[b * T_N + threadIdx.x] & 0xFFFFFFFFull));
    __syncthreads();

    float im = g_iou_max[b * A_N + a];
    int cls = -1;
    if (im < 0.3f) cls = 0;
    bool isb = false;
    #pragma unroll
    for (int g = 0; g < T_N; ++g) isb |= (sba[g] == a);
    if (isb || im >= 0.7f) cls = 1;
    g_cls0[b * A_N + a] = (signed char)cls;
}

// kth smallest 64-bit key (value_bits<<32 | index) among {i : cls[i]==want}; exact (keys unique).
__device__ __forceinline__ ull radix_select(const float* __restrict__ r,
                                            const signed char* __restrict__ cls,
                                            int want, int k, int* hist, int* sh) {
    ull prefix = 0;
    const int tid = threadIdx.x;
    for (int byte = 7; byte >= 0; --byte) {
        const int shift = byte * 8;
        if (tid < 256) hist[tid] = 0;
        __syncthreads();
        for (int i = tid; i < A_N; i += blockDim.x) {
            if (cls[i] == want) {
                ull key = ((ull)__float_as_uint(r[i]) << 32) | (unsigned)i;
                bool match = (byte == 7) || ((key >> (shift + 8)) == (prefix >> (shift + 8)));
                if (match) atomicAdd(&hist[(int)((key >> shift) & 0xFF)], 1);
            }
        }
        __syncthreads();
        if (tid == 0) {
            int cum = 0, d = 0;
            for (; d < 255; ++d) {
                if (cum + hist[d] >= k) break;
                cum += hist[d];
            }
            sh[0] = d;
            sh[1] = k - cum;
        }
        __syncthreads();
        prefix |= ((ull)sh[0]) << shift;
        k = sh[1];
        __syncthreads();
    }
    return prefix;
}

__global__ void k_select(const float* __restrict__ rpos, const float* __restrict__ rneg) {
    const int b = blockIdx.x;
    const signed char* cls = g_cls0 + b * A_N;
    const float* rp = rpos + b * A_N;
    const float* rn = rneg + b * A_N;

    __shared__ int hist[256];
    __shared__ int sh[2];
    __shared__ int cnt[2];
    const int tid = threadIdx.x;
    if (tid < 2) cnt[tid] = 0;
    __syncthreads();

    int cp = 0, cn = 0;
    for (int i = tid; i < A_N; i += blockDim.x) {
        int c = cls[i];
        cp += (c == 1);
        cn += (c == 0);
    }
    atomicAdd(&cnt[0], cp);
    atomicAdd(&cnt[1], cn);
    __syncthreads();
    const int P  = cnt[0];
    const int Nn = cnt[1];

    ull pth = ~0ull;
    if (P > 128) pth = radix_select(rp, cls, 1, 128, hist, sh);
    const int npos    = (P < 128) ? P : 128;
    const int desired = 256 - npos;
    ull nth = ~0ull;
    if (Nn > desired) nth = radix_select(rn, cls, 0, desired, hist, sh);

    if (tid == 0) { g_thresh[b * 2] = pth; g_thresh[b * 2 + 1] = nth; }
}

__global__ void k_out(const float4* __restrict__ anchors, const float4* __restrict__ gts,
                      const float* __restrict__ rpos, const float* __restrict__ rneg,
                      float* __restrict__ out) {
    const int b = blockIdx.y;
    const int a = blockIdx.x * blockDim.x + threadIdx.x;
    const int i = b * A_N + a;

    int cls = g_cls0[i];
    if (cls == 1) {
        ull key = ((ull)__float_as_uint(rpos[i]) << 32) | (unsigned)a;
        if (key > g_thresh[b * 2]) cls = -1;
    } else if (cls == 0) {
        ull key = ((ull)__float_as_uint(rneg[i]) << 32) | (unsigned)a;
        if (key > g_thresh[b * 2 + 1]) cls = -1;
    }
    out[i] = (float)cls;

    float4 d = make_float4(0.f, 0.f, 0.f, 0.f);
    if (cls == 1) {
        float4 box = anchors[i];
        bool inb = (box.x >= 0.f) && (box.y >= 0.f) && (box.z <= 1.f) && (box.w <= 1.f);
        if (!inb) { box.x = box.y = box.z = box.w = 0.f; }
        float4 gt = gts[b * T_N + g_best_g[i]];
        float ah = box.z - box.x, aw = box.w - box.y;
        float acy = box.x + 0.5f * ah, acx = box.y + 0.5f * aw;
        float gh = gt.z - gt.x, gw = gt.w - gt.y;
        float gcy = gt.x + 0.5f * gh, gcx = gt.y + 0.5f * gw;
        float ahs = (ah > 0.f) ? ah : 1.f;
        float aws = (aw > 0.f) ? aw : 1.f;
        float ghs = (gh > 0.f) ? gh : 1.f;
        float gws = (gw > 0.f) ? gw : 1.f;
        d.x = __fdiv_rn(gcy - acy, ahs);
        d.y = __fdiv_rn(gcx - acx, aws);
        d.z = logf(__fdiv_rn(ghs, ahs));
        d.w = logf(__fdiv_rn(gws, aws));
    }
    reinterpret_cast<float4*>(out + (size_t)N_B * A_N)[i] = d;
}

extern "C" void kernel_launch(void* const* d_in, const int* in_sizes, int n_in,
                              void* d_out, int out_size) {
    const float4* anchors = (const float4*)d_in[0];
    const float4* gts     = (const float4*)d_in[1];
    const float*  rp      = (const float*)d_in[2];
    const float*  rn      = (const float*)d_in[3];
    float* out = (float*)d_out;

    dim3 grid(A_N / 256, N_B);
    k_init<<<1, 512>>>();
    k_iou<<<grid, 256>>>(anchors, gts);
    k_cls<<<grid, 256>>>();
    k_select<<<N_B, 1024>>>(rp, rn);
    k_out<<<grid, 256>>>(anchors, gts, rp, rn, out);
}

// round 2
// speedup vs baseline: 1.5089x; 1.5089x over previous
#include <cuda_runtime.h>

#define N_B 8
#define A_N 131072
#define T_N 64
#define BINS 4096
#define CAND_MAX 4096
typedef unsigned long long ull;

// Scratch (static __device__ — no allocations allowed)
__device__ ull           g_gt_best[N_B * T_N];        // packed (iou_bits<<32 | ~anchor)
__device__ float         g_iou_max[N_B * A_N];
__device__ unsigned char g_best_g [N_B * A_N];
__device__ signed char   g_cls0  [N_B * A_N];
__device__ ull           g_thresh[N_B * 2];           // [pos_th, neg_th] per batch
__device__ int           g_hist  [N_B * 2 * BINS];    // value histograms (pos, neg)
__device__ int           g_binres[N_B * 2 * 2];       // (bin, residual) per (b,type)
__device__ ull           g_cand  [N_B * 2 * CAND_MAX];
__device__ int           g_ccnt  [N_B * 2];

__global__ void k_init() {
    int i = blockIdx.x * blockDim.x + threadIdx.x;
    if (i < N_B * T_N) g_gt_best[i] = 0ull;
    if (i < N_B * 2 * BINS) g_hist[i] = 0;
    if (i < N_B * 2) g_ccnt[i] = 0;
}

__global__ void k_iou(const float4* __restrict__ anchors, const float4* __restrict__ gts) {
    const int b   = blockIdx.y;
    const int a   = blockIdx.x * blockDim.x + threadIdx.x;
    const int tid = threadIdx.x;

    __shared__ float sy1[T_N], sx1[T_N], sy2[T_N], sx2[T_N], sga[T_N];
    __shared__ ull   sbest[T_N];

    if (tid < T_N) {
        float4 g = gts[b * T_N + tid];
        sy1[tid] = g.x; sx1[tid] = g.y; sy2[tid] = g.z; sx2[tid] = g.w;
        sga[tid] = (g.z - g.x) * (g.w - g.y);
        sbest[tid] = 0ull;
    }
    __syncthreads();

    float4 box = anchors[b * A_N + a];
    bool inb = (box.x >= 0.f) && (box.y >= 0.f) && (box.z <= 1.f) && (box.w <= 1.f);
    if (!inb) { box.x = box.y = box.z = box.w = 0.f; }
    const float aarea = (box.z - box.x) * (box.w - box.y);

    float mymax = -1.f;
    int   myg   = 0;
    const unsigned ainv = 0xFFFFFFFFu - (unsigned)a;  // max-key => min anchor idx (first-max tie-break)

    #pragma unroll
    for (int g = 0; g < T_N; ++g) {
        float ih = fminf(box.z, sy2[g]) - fmaxf(box.x, sy1[g]);
        float iw = fminf(box.w, sx2[g]) - fmaxf(box.y, sx1[g]);
        ih = fmaxf(ih, 0.f);
        iw = fmaxf(iw, 0.f);
        float inter = ih * iw;
        float iou = 0.f;
        if (inter > 0.f) {
            float un = aarea + sga[g] - inter;     // un >= garea > 0 whenever inter > 0
            iou = __fdiv_rn(inter, un);            // IEEE: match XLA's div exactly
        }
        if (iou > mymax) { mymax = iou; myg = g; } // strict > => first-max argmax over g
        ull key = ((ull)__float_as_uint(iou) << 32) | ainv;
        if (key > sbest[g]) atomicMax(&sbest[g], key);  // read-filter then shared atomic
    }

    g_iou_max[b * A_N + a] = mymax;
    g_best_g [b * A_N + a] = (unsigned char)myg;

    __syncthreads();
    if (tid < T_N && sbest[tid]) atomicMax(&g_gt_best[b * T_N + tid], sbest[tid]);
}

__device__ __forceinline__ int val_bin(float v) {
    int bin = (int)(v * (float)BINS);
    return bin > (BINS - 1) ? (BINS - 1) : (bin < 0 ? 0 : bin);
}

__global__ void k_cls(const float* __restrict__ rpos, const float* __restrict__ rneg) {
    const int b = blockIdx.y;
    const int a = blockIdx.x * blockDim.x + threadIdx.x;
    __shared__ int sba[T_N];
    if (threadIdx.x < T_N)
        sba[threadIdx.x] =
            (int)(0xFFFFFFFFu - (unsigned)(g_gt_best[b * T_N + threadIdx.x] & 0xFFFFFFFFull));
    __syncthreads();

    float im = g_iou_max[b * A_N + a];
    int cls = -1;
    if (im < 0.3f) cls = 0;
    bool isb = false;
    #pragma unroll
    for (int g = 0; g < T_N; ++g) isb |= (sba[g] == a);
    if (isb || im >= 0.7f) cls = 1;
    g_cls0[b * A_N + a] = (signed char)cls;

    // fused histogram for rank selection
    if (cls == 1) atomicAdd(&g_hist[(b * 2 + 0) * BINS + val_bin(rpos[b * A_N + a])], 1);
    else if (cls == 0) atomicAdd(&g_hist[(b * 2 + 1) * BINS + val_bin(rneg[b * A_N + a])], 1);
}

// Find bin containing the k-th smallest (1-based) masked element; returns bin or -1
// if total <= k (no threshold needed). residual = rank within bin. Also outputs total.
__device__ int find_kth_bin(const int* __restrict__ hist, int k, int* residual, int* total_out,
                            int* part, int* sres) {
    const int tid = threadIdx.x;
    const int base = tid * 4;
    int s0 = hist[base], s1 = hist[base + 1], s2 = hist[base + 2], s3 = hist[base + 3];
    int mysum = s0 + s1 + s2 + s3;
    part[tid] = mysum;
    __syncthreads();
    for (int off = 1; off < 1024; off <<= 1) {
        int v = (tid >= off) ? part[tid - off] : 0;
        __syncthreads();
        part[tid] += v;
        __syncthreads();
    }
    int total = part[1023];
    if (tid == 0) { sres[0] = -1; sres[1] = 0; }
    __syncthreads();
    if (total > k && k >= 1) {
        int incl = part[tid];
        int before = incl - mysum;
        if (before < k && k <= incl) {   // unique thread
            int c = before, bsel, res;
            if (k <= c + s0)      { bsel = base;     res = k - c; }
            else { c += s0; if (k <= c + s1) { bsel = base + 1; res = k - c; }
            else { c += s1; if (k <= c + s2) { bsel = base + 2; res = k - c; }
            else { c += s2;        bsel = base + 3; res = k - c; } } }
            sres[0] = bsel; sres[1] = res;
        }
    }
    __syncthreads();
    *residual  = sres[1];
    *total_out = total;
    return sres[0];
}

__global__ void k_pick() {
    const int b = blockIdx.x;
    __shared__ int part[1024];
    __shared__ int sres[2];
    int res, P;
    int bin_p = find_kth_bin(g_hist + (b * 2 + 0) * BINS, 128, &res, &P, part, sres);
    if (threadIdx.x == 0) {
        g_binres[(b * 2 + 0) * 2]     = bin_p;
        g_binres[(b * 2 + 0) * 2 + 1] = res;
        if (bin_p < 0) g_thresh[b * 2] = ~0ull;   // keep all positives
    }
    __syncthreads();
    const int npos    = (P < 128) ? P : 128;
    const int desired = 256 - npos;
    int Nn;
    int bin_n = find_kth_bin(g_hist + (b * 2 + 1) * BINS, desired, &res, &Nn, part, sres);
    if (threadIdx.x == 0) {
        g_binres[(b * 2 + 1) * 2]     = bin_n;
        g_binres[(b * 2 + 1) * 2 + 1] = res;
        if (bin_n < 0) g_thresh[b * 2 + 1] = ~0ull;
    }
}

__global__ void k_gather(const float* __restrict__ rpos, const float* __restrict__ rneg) {
    const int b = blockIdx.y;
    const int a = blockIdx.x * blockDim.x + threadIdx.x;
    const int i = b * A_N + a;
    int cls = g_cls0[i];
    if (cls < 0) return;
    const int type = (cls == 1) ? 0 : 1;
    const int tb   = g_binres[(b * 2 + type) * 2];
    if (tb < 0) return;
    float v = (type == 0) ? rpos[i] : rneg[i];
    if (val_bin(v) == tb) {
        int slot = atomicAdd(&g_ccnt[b * 2 + type], 1);
        if (slot < CAND_MAX)
            g_cand[(b * 2 + type) * CAND_MAX + slot] = ((ull)__float_as_uint(v) << 32) | (unsigned)a;
    }
}

__global__ void k_thresh() {
    const int bt  = blockIdx.x;              // (b*2 + type)
    const int bin = g_binres[bt * 2];
    if (bin < 0) return;                     // thresh already set by k_pick
    const int m   = g_binres[bt * 2 + 1];    // 1-based rank within bin
    int C = g_ccnt[bt];
    if (C > CAND_MAX) C = CAND_MAX;
    __shared__ ull sk[CAND_MAX];
    for (int i = threadIdx.x; i < C; i += blockDim.x) sk[i] = g_cand[bt * CAND_MAX + i];
    __syncthreads();
    for (int i = threadIdx.x; i < C; i += blockDim.x) {
        ull me = sk[i];
        int cnt = 0;
        for (int j = 0; j < C; ++j) cnt += (sk[j] < me);
        if (cnt == m - 1) g_thresh[bt] = me;   // keys unique -> exactly one writer
    }
}

__global__ void k_out(const float4* __restrict__ anchors, const float4* __restrict__ gts,
                      const float* __restrict__ rpos, const float* __restrict__ rneg,
                      float* __restrict__ out) {
    const int b = blockIdx.y;
    const int a = blockIdx.x * blockDim.x + threadIdx.x;
    const int i = b * A_N + a;

    int cls = g_cls0[i];
    if (cls == 1) {
        ull key = ((ull)__float_as_uint(rpos[i]) << 32) | (unsigned)a;
        if (key > g_thresh[b * 2]) cls = -1;
    } else if (cls == 0) {
        ull key = ((ull)__float_as_uint(rneg[i]) << 32) | (unsigned)a;
        if (key > g_thresh[b * 2 + 1]) cls = -1;
    }
    out[i] = (float)cls;

    float4 d = make_float4(0.f, 0.f, 0.f, 0.f);
    if (cls == 1) {
        float4 box = anchors[i];
        bool inb = (box.x >= 0.f) && (box.y >= 0.f) && (box.z <= 1.f) && (box.w <= 1.f);
        if (!inb) { box.x = box.y = box.z = box.w = 0.f; }
        float4 gt = gts[b * T_N + g_best_g[i]];
        float ah = box.z - box.x, aw = box.w - box.y;
        float acy = box.x + 0.5f * ah, acx = box.y + 0.5f * aw;
        float gh = gt.z - gt.x, gw = gt.w - gt.y;
        float gcy = gt.x + 0.5f * gh, gcx = gt.y + 0.5f * gw;
        float ahs = (ah > 0.f) ? ah : 1.f;
        float aws = (aw > 0.f) ? aw : 1.f;
        float ghs = (gh > 0.f) ? gh : 1.f;
        float gws = (gw > 0.f) ? gw : 1.f;
        d.x = __fdiv_rn(gcy - acy, ahs);
        d.y = __fdiv_rn(gcx - acx, aws);
        d.z = logf(__fdiv_rn(ghs, ahs));
        d.w = logf(__fdiv_rn(gws, aws));
    }
    reinterpret_cast<float4*>(out + (size_t)N_B * A_N)[i] = d;
}

extern "C" void kernel_launch(void* const* d_in, const int* in_sizes, int n_in,
                              void* d_out, int out_size) {
    const float4* anchors = (const float4*)d_in[0];
    const float4* gts     = (const float4*)d_in[1];
    const float*  rp      = (const float*)d_in[2];
    const float*  rn      = (const float*)d_in[3];
    float* out = (float*)d_out;

    dim3 grid(A_N / 256, N_B);
    k_init<<<(N_B * 2 * BINS + 511) / 512, 512>>>();
    k_iou<<<grid, 256>>>(anchors, gts);
    k_cls<<<grid, 256>>>(rp, rn);
    k_pick<<<N_B, 1024>>>();
    k_gather<<<grid, 256>>>(rp, rn);
    k_thresh<<<N_B * 2, 1024>>>();
    k_out<<<grid, 256>>>(anchors, gts, rp, rn, out);
}